// round 6
// baseline (speedup 1.0000x reference)
#include <cuda_runtime.h>
#include <stdint.h>

// ---------------- problem constants ----------------
#define BB 4
#define CC 19
#define SH 97
#define SW 97
#define OH 769
#define OW 769
#define PLANE (SH*SW)                    // 9409
#define NPIX (BB*OH*OW)                  // 2,365,444
#define SPR ((OW+7)/8)                   // 97 strips per row
#define NSTRIPS (BB*OH*SPR)              // 298,372
#define PRED_ELEMS (BB*CC*SH*SW)         // 715,084
#define MINKEPT 100000
#define IGN 255
#define LOG_THR (-0.356674943938732f)    // ln(0.7)

__constant__ float c_w[CC] = {
    0.8373f, 0.918f,  0.866f,  1.0345f, 1.0166f, 0.9969f, 0.9754f,
    1.0489f, 0.8786f, 1.0023f, 0.9539f, 0.9843f, 1.1116f, 0.9037f,
    1.0865f, 1.0955f, 1.0865f, 1.1529f, 1.0507f};

// ---------------- device scratch (static: no allocation) ----------------
__device__ uint32_t     g_keys[2][NPIX];        // order-preserving keys of log p_true
__device__ uint8_t      g_cls[NPIX];            // class idx (255 = invalid)
__device__ unsigned int g_hist[2][4][256];
__device__ unsigned int g_prefix[2];
__device__ int          g_krem[2];
__device__ unsigned int g_numvalid;
__device__ double       g_sums[4];              // sw1, swl1, sw2, swl2
__device__ float        g_logth[2];             // log-domain keep threshold
__device__ int          g_keepall;
__device__ int          g_is64;

// monotone float<->uint transform (total order, negatives reversed)
__device__ __forceinline__ uint32_t f2key(float f) {
    uint32_t u = __float_as_uint(f);
    return u ^ ((u & 0x80000000u) ? 0xFFFFFFFFu : 0x80000000u);
}
__device__ __forceinline__ float key2f(uint32_t k) {
    uint32_t u = (k & 0x80000000u) ? (k ^ 0x80000000u) : ~k;
    return __uint_as_float(u);
}

// ---------------- init ----------------
__global__ void init_kernel() {
    int i = threadIdx.x;
    unsigned int* h = &g_hist[0][0][0];
    for (int j = i; j < 2 * 4 * 256; j += blockDim.x) h[j] = 0u;
    if (i < 4) g_sums[i] = 0.0;
    if (i < 2) { g_prefix[i] = 0u; g_krem[i] = 0; g_logth[i] = LOG_THR; }
    if (i == 0) { g_numvalid = 0u; g_keepall = 0; }
}

// int64-vs-int32 target detection: little-endian int64 labels < 2^31 have
// every odd 32-bit word == 0. For int32 random labels in [0,19) the chance
// all 64 odd words are 0 is (1/19)^64 ~ 0.
__global__ void detect_kernel(const int* __restrict__ t) {
    if (threadIdx.x == 0 && blockIdx.x == 0) {
        int nz = 0;
        for (int i = 1; i < 128; i += 2) nz += (t[i] != 0);
        g_is64 = (nz == 0) ? 1 : 0;
    }
}

// ---------------- main fused kernel ----------------
// One thread = 8 consecutive output-x pixels in one output row (one strip).
// 8 output px span < 1 source column step, so 3 source cols x 2 rows per
// channel serve the whole strip (ix differs by at most 1 within a strip).
// Also builds the radix-select pass-0 (top byte) histograms in shared memory
// and writes a uint8 class-index array for the final reduction.
__global__ void __launch_bounds__(128) main_kernel(
    const float* __restrict__ p1, const float* __restrict__ p2,
    const void* __restrict__ tgt)
{
    __shared__ unsigned int sh_hist[2][256];
    for (int i = threadIdx.x; i < 512; i += blockDim.x)
        (&sh_hist[0][0])[i] = 0u;
    __syncthreads();

    int sid = blockIdx.x * blockDim.x + threadIdx.x;
    int validcnt = 0;
    if (sid < NSTRIPS) {
        int row = sid / SPR;
        int xs  = (sid - row * SPR) * 8;
        int b   = row / OH;
        int y   = row - b * OH;

        const float SCALE = (float)(97.0 / 769.0);

        // vertical interpolation (shared by whole strip)
        float sy  = ((float)y + 0.5f) * SCALE - 0.5f;
        float iyf = floorf(sy);
        int   iy  = (int)iyf;
        float fy  = sy - iyf;
        if (iy < 0)      { iy = 0;      fy = 0.f; }
        if (iy > SH - 2) { iy = SH - 2; fy = 1.f; }

        int npix = OW - xs; if (npix > 8) npix = 8;

        // horizontal positions; tail pixels duplicate the last real one
        float fx[8]; int omask = 0; int a = 0;
        #pragma unroll
        for (int j = 0; j < 8; j++) {
            int xj = xs + ((j < npix) ? j : (npix - 1));
            float sx  = ((float)xj + 0.5f) * SCALE - 0.5f;
            float ixf = floorf(sx);
            int   ix  = (int)ixf;
            float f   = sx - ixf;
            if (ix < 0)      { ix = 0;      f = 0.f; }
            if (ix > SW - 2) { ix = SW - 2; f = 1.f; }
            if (j == 0) a = ix;
            fx[j] = f;
            omask |= (ix - a) << j;      // 0 or 1
        }
        int off2 = (a + 2 <= SW - 1) ? 2 : 1;   // keep 3rd column load in-bounds

        long long pixbase = ((long long)(b * OH + y)) * OW + xs;

        // targets + class-index array
        int ts[8]; int vmask = 0;
        int is64 = g_is64;
        #pragma unroll
        for (int j = 0; j < 8; j++) {
            int t = IGN;
            if (j < npix) {
                t = is64 ? (int)((const long long*)tgt)[pixbase + j]
                         : ((const int*)tgt)[pixbase + j];
            }
            int v = (t != IGN);
            vmask |= v << j;
            validcnt += v;
            int tc = (t < 0 ? 0 : (t > CC - 1 ? CC - 1 : t));
            ts[j] = v ? tc : -1;
            if (j < npix) g_cls[pixbase + j] = (uint8_t)(v ? tc : 255);
        }

        const float* preds[2] = { p1, p2 };
        #pragma unroll 1
        for (int pi = 0; pi < 2; pi++) {
            const float* base = preds[pi] + ((long long)b * CC) * PLANE + iy * SW + a;
            float s[8], zt[8];
            #pragma unroll
            for (int j = 0; j < 8; j++) { s[j] = 0.f; zt[j] = 0.f; }

            #pragma unroll 1
            for (int c = 0; c < CC; c++) {
                const float* r0 = base + c * PLANE;
                float r00 = __ldg(r0 + 0),  r01 = __ldg(r0 + 1),  r02 = __ldg(r0 + off2);
                float r10 = __ldg(r0 + SW), r11 = __ldg(r0 + SW + 1), r12 = __ldg(r0 + SW + off2);
                float h0 = fmaf(fy, r10 - r00, r00);
                float h1 = fmaf(fy, r11 - r01, r01);
                float h2 = fmaf(fy, r12 - r02, r02);
                float d0 = h1 - h0, d1 = h2 - h1;
                #pragma unroll
                for (int j = 0; j < 8; j++) {
                    float bb = ((omask >> j) & 1) ? h1 : h0;
                    float dd = ((omask >> j) & 1) ? d1 : d0;
                    float z  = fmaf(fx[j], dd, bb);
                    s[j] += __expf(z);                 // no max-sub: |z| small
                    zt[j] = (ts[j] == c) ? z : zt[j];
                }
            }

            #pragma unroll
            for (int j = 0; j < 8; j++) {
                if (j < npix) {
                    float lp = zt[j] - __logf(s[j]);
                    uint32_t k = ((vmask >> j) & 1) ? f2key(lp) : 0xFFFFFFFFu;
                    g_keys[pi][pixbase + j] = k;
                    atomicAdd(&sh_hist[pi][k >> 24], 1u);   // radix pass 0, fused
                }
            }
        }
    }
    unsigned int wsum = __reduce_add_sync(0xFFFFFFFFu, (unsigned int)validcnt);
    if ((threadIdx.x & 31) == 0 && wsum) atomicAdd(&g_numvalid, wsum);

    __syncthreads();
    for (int i = threadIdx.x; i < 512; i += blockDim.x) {
        unsigned int v = (&sh_hist[0][0])[i];
        if (v) atomicAdd(&g_hist[i >> 8][0][i & 255], v);
    }
}

// ---------------- radix select passes 1..3 ----------------
// NPIX = 2,365,444 = 4 * 591,361 -> exact uint4 coverage.
#define NPIX4 (NPIX/4)
__global__ void hist_kernel(int pass) {
    __shared__ unsigned int sh[256];
    int pred = blockIdx.y;
    for (int i = threadIdx.x; i < 256; i += blockDim.x) sh[i] = 0u;
    __syncthreads();
    unsigned int pref = g_prefix[pred];
    int shift = 24 - 8 * pass;
    const uint4* keys4 = (const uint4*)&g_keys[pred][0];
    for (long long i = (long long)blockIdx.x * blockDim.x + threadIdx.x; i < NPIX4;
         i += (long long)gridDim.x * blockDim.x) {
        uint4 kv = __ldg(keys4 + i);
        if ((kv.x >> (shift + 8)) == pref) atomicAdd(&sh[(kv.x >> shift) & 255u], 1u);
        if ((kv.y >> (shift + 8)) == pref) atomicAdd(&sh[(kv.y >> shift) & 255u], 1u);
        if ((kv.z >> (shift + 8)) == pref) atomicAdd(&sh[(kv.z >> shift) & 255u], 1u);
        if ((kv.w >> (shift + 8)) == pref) atomicAdd(&sh[(kv.w >> shift) & 255u], 1u);
    }
    __syncthreads();
    for (int i = threadIdx.x; i < 256; i += blockDim.x) {
        unsigned int v = sh[i];
        if (v) atomicAdd(&g_hist[pred][pass][i], v);
    }
}

__global__ void find_kernel(int pass) {
    if (threadIdx.x == 0 && blockIdx.x == 0) {
        for (int pred = 0; pred < 2; pred++) {
            long long kr;
            if (pass == 0) {
                unsigned int nv = g_numvalid;
                long long kk = (long long)(nv < (unsigned)MINKEPT ? nv : (unsigned)MINKEPT) - 1;
                if (kk < 0) kk = 0;
                kr = kk;
                g_keepall = ((unsigned)MINKEPT >= nv) ? 1 : 0;
            } else {
                kr = g_krem[pred];
            }
            const unsigned int* h = g_hist[pred][pass];
            int bsel = 255;
            for (int bn = 0; bn < 256; bn++) {
                unsigned int cn = h[bn];
                if (kr < (long long)cn) { bsel = bn; break; }
                kr -= cn;
            }
            g_prefix[pred] = ((pass == 0) ? 0u : (g_prefix[pred] << 8)) | (unsigned)bsel;
            g_krem[pred] = (int)kr;
            if (pass == 3) {
                // log-domain threshold: max(lp_kth, ln 0.7). Monotone-exact:
                // p <= max(p_kth, 0.7)  <=>  lp <= max(lp_kth, ln 0.7)
                float lp = key2f(g_prefix[pred]);
                g_logth[pred] = (lp > LOG_THR) ? lp : LOG_THR;
            }
        }
    }
}

// ---------------- final weighted reduction ----------------
__global__ void sum_kernel() {
    int pred = blockIdx.y;
    int keepall = g_keepall;
    float lth = g_logth[pred];
    float sw = 0.f, swl = 0.f;
    for (long long i = (long long)blockIdx.x * blockDim.x + threadIdx.x; i < NPIX;
         i += (long long)gridDim.x * blockDim.x) {
        uint32_t k = g_keys[pred][i];
        if (k == 0xFFFFFFFFu) continue;                // invalid pixel
        float lp = key2f(k);
        if (!keepall && (lp > lth)) continue;          // OHEM filter (log-domain)
        float w = c_w[g_cls[i]];
        sw += w; swl += w * (-lp);
    }
    // warp shuffle reduction, then 8-lane smem combine
    #pragma unroll
    for (int st = 16; st > 0; st >>= 1) {
        sw  += __shfl_down_sync(0xFFFFFFFFu, sw, st);
        swl += __shfl_down_sync(0xFFFFFFFFu, swl, st);
    }
    __shared__ float red[2][8];
    int wid = threadIdx.x >> 5, lid = threadIdx.x & 31;
    if (lid == 0) { red[0][wid] = sw; red[1][wid] = swl; }
    __syncthreads();
    if (wid == 0) {
        sw  = (lid < (blockDim.x >> 5)) ? red[0][lid] : 0.f;
        swl = (lid < (blockDim.x >> 5)) ? red[1][lid] : 0.f;
        #pragma unroll
        for (int st = 4; st > 0; st >>= 1) {
            sw  += __shfl_down_sync(0xFFu, sw, st);
            swl += __shfl_down_sync(0xFFu, swl, st);
        }
        if (lid == 0) {
            atomicAdd(&g_sums[pred * 2 + 0], (double)sw);
            atomicAdd(&g_sums[pred * 2 + 1], (double)swl);
        }
    }
}

__global__ void fin_kernel(float* out) {
    if (threadIdx.x == 0 && blockIdx.x == 0) {
        float L1 = (float)(g_sums[1] / g_sums[0]);
        float L2 = (float)(g_sums[3] / g_sums[2]);
        out[0] = 0.4f * L1 + L2;
    }
}

// ---------------- launch ----------------
extern "C" void kernel_launch(void* const* d_in, const int* in_sizes, int n_in,
                              void* d_out, int out_size)
{
    // identify inputs: preds have exactly PRED_ELEMS elements (unique count);
    // the target is whatever remains (size NPIX for int32/int64 element counts,
    // or 2*NPIX if the harness reports int64 as 32-bit words).
    const float* preds[2] = { nullptr, nullptr };
    const void* tg = nullptr;
    int pi = 0;
    for (int i = 0; i < n_in && i < 3; i++) {
        if (in_sizes[i] == PRED_ELEMS && pi < 2) preds[pi++] = (const float*)d_in[i];
        else tg = d_in[i];
    }
    // positional fallback (metadata order: pred1, pred2, target)
    if (!tg || pi < 2) {
        preds[0] = (const float*)d_in[0];
        preds[1] = (const float*)d_in[1];
        tg = d_in[2];
    }

    init_kernel<<<1, 256>>>();
    detect_kernel<<<1, 32>>>((const int*)tg);

    int nb = (NSTRIPS + 127) / 128;
    main_kernel<<<nb, 128>>>(preds[0], preds[1], tg);

    find_kernel<<<1, 32>>>(0);                    // pass-0 hist fused into main
    for (int pass = 1; pass < 4; pass++) {
        hist_kernel<<<dim3(512, 2), 256>>>(pass);
        find_kernel<<<1, 32>>>(pass);
    }

    sum_kernel<<<dim3(512, 2), 256>>>();
    fin_kernel<<<1, 32>>>((float*)d_out);
}

// round 10
// speedup vs baseline: 1.4775x; 1.4775x over previous
#include <cuda_runtime.h>
#include <stdint.h>

// ---------------- problem constants ----------------
#define BB 4
#define CC 19
#define SH 97
#define SW 97
#define OH 769
#define OW 769
#define PLANE (SH*SW)                    // 9409
#define NPIX (BB*OH*OW)                  // 2,365,444
#define SPR ((OW+7)/8)                   // 97 strips per row
#define NSTRIPS (BB*OH*SPR)              // 298,372
#define PRED_ELEMS (BB*CC*SH*SW)         // 715,084
#define MINKEPT 100000
#define IGN 255
#define LOG_THR (-0.356674943938732f)    // ln(0.7)
#define SUM_BLOCKS 512                   // x-dim of sum grid (y=2 preds)

__constant__ float c_w[CC] = {
    0.8373f, 0.918f,  0.866f,  1.0345f, 1.0166f, 0.9969f, 0.9754f,
    1.0489f, 0.8786f, 1.0023f, 0.9539f, 0.9843f, 1.1116f, 0.9037f,
    1.0865f, 1.0955f, 1.0865f, 1.1529f, 1.0507f};

// ---------------- device scratch (static: no allocation) ----------------
__device__ uint32_t     g_keys[2][NPIX];        // order-preserving keys of log p_true
__device__ uint8_t      g_cls[NPIX];            // class idx (255 = invalid)
__device__ unsigned int g_hist[2][4][256];
__device__ unsigned int g_prefix[2];
__device__ int          g_krem[2];
__device__ unsigned int g_numvalid;
__device__ double       g_sums[4];              // sw1, swl1, sw2, swl2
__device__ float        g_logth[2];             // log-domain keep threshold
__device__ int          g_keepall;
__device__ int          g_is64;
__device__ unsigned int g_bdone;                // sum_kernel completion counter

// monotone float<->uint transform (total order, negatives reversed)
__device__ __forceinline__ uint32_t f2key(float f) {
    uint32_t u = __float_as_uint(f);
    return u ^ ((u & 0x80000000u) ? 0xFFFFFFFFu : 0x80000000u);
}
__device__ __forceinline__ float key2f(uint32_t k) {
    uint32_t u = (k & 0x80000000u) ? (k ^ 0x80000000u) : ~k;
    return __uint_as_float(u);
}

// ---------------- init (+ int64 target detection fused) ----------------
// int64-vs-int32: little-endian int64 labels < 2^31 have every odd 32-bit
// word == 0. For int32 random labels in [0,19) the chance all 64 odd words
// are 0 is (1/19)^64 ~ 0.
__global__ void init_kernel(const int* __restrict__ t) {
    int i = threadIdx.x;
    unsigned int* h = &g_hist[0][0][0];
    for (int j = i; j < 2 * 4 * 256; j += blockDim.x) h[j] = 0u;
    if (i < 4) g_sums[i] = 0.0;
    if (i < 2) { g_prefix[i] = 0u; g_krem[i] = 0; g_logth[i] = LOG_THR; }
    if (i == 0) { g_numvalid = 0u; g_keepall = 0; g_bdone = 0u; }
    if (i == 32) {                       // separate warp: detection
        int nz = 0;
        for (int k = 1; k < 128; k += 2) nz += (t[k] != 0);
        g_is64 = (nz == 0) ? 1 : 0;
    }
}

// ---------------- main fused kernel ----------------
// One thread = 8 consecutive output-x pixels in one output row (one strip).
// 8 output px span < 1 source column step, so 3 source cols x 2 rows per
// channel serve the whole strip (ix differs by at most 1 within a strip).
// Also builds the radix-select pass-0 (top byte) histograms in shared memory
// and writes a uint8 class-index array for the final reduction.
__global__ void __launch_bounds__(128) main_kernel(
    const float* __restrict__ p1, const float* __restrict__ p2,
    const void* __restrict__ tgt)
{
    __shared__ unsigned int sh_hist[2][256];
    for (int i = threadIdx.x; i < 512; i += blockDim.x)
        (&sh_hist[0][0])[i] = 0u;
    __syncthreads();

    int sid = blockIdx.x * blockDim.x + threadIdx.x;
    int validcnt = 0;
    if (sid < NSTRIPS) {
        int row = sid / SPR;
        int xs  = (sid - row * SPR) * 8;
        int b   = row / OH;
        int y   = row - b * OH;

        const float SCALE = (float)(97.0 / 769.0);

        // vertical interpolation (shared by whole strip)
        float sy  = ((float)y + 0.5f) * SCALE - 0.5f;
        float iyf = floorf(sy);
        int   iy  = (int)iyf;
        float fy  = sy - iyf;
        if (iy < 0)      { iy = 0;      fy = 0.f; }
        if (iy > SH - 2) { iy = SH - 2; fy = 1.f; }

        int npix = OW - xs; if (npix > 8) npix = 8;

        // horizontal positions; tail pixels duplicate the last real one
        float fx[8]; int omask = 0; int a = 0;
        #pragma unroll
        for (int j = 0; j < 8; j++) {
            int xj = xs + ((j < npix) ? j : (npix - 1));
            float sx  = ((float)xj + 0.5f) * SCALE - 0.5f;
            float ixf = floorf(sx);
            int   ix  = (int)ixf;
            float f   = sx - ixf;
            if (ix < 0)      { ix = 0;      f = 0.f; }
            if (ix > SW - 2) { ix = SW - 2; f = 1.f; }
            if (j == 0) a = ix;
            fx[j] = f;
            omask |= (ix - a) << j;      // 0 or 1
        }
        int off2 = (a + 2 <= SW - 1) ? 2 : 1;   // keep 3rd column load in-bounds

        long long pixbase = ((long long)(b * OH + y)) * OW + xs;

        // targets + class-index array
        int ts[8]; int vmask = 0;
        int is64 = g_is64;
        #pragma unroll
        for (int j = 0; j < 8; j++) {
            int t = IGN;
            if (j < npix) {
                t = is64 ? (int)((const long long*)tgt)[pixbase + j]
                         : ((const int*)tgt)[pixbase + j];
            }
            int v = (t != IGN);
            vmask |= v << j;
            validcnt += v;
            int tc = (t < 0 ? 0 : (t > CC - 1 ? CC - 1 : t));
            ts[j] = v ? tc : -1;
            if (j < npix) g_cls[pixbase + j] = (uint8_t)(v ? tc : 255);
        }

        const float* preds[2] = { p1, p2 };
        #pragma unroll 1
        for (int pi = 0; pi < 2; pi++) {
            const float* base = preds[pi] + ((long long)b * CC) * PLANE + iy * SW + a;
            float s[8], zt[8];
            #pragma unroll
            for (int j = 0; j < 8; j++) { s[j] = 0.f; zt[j] = 0.f; }

            // unroll 2: doubles in-flight LDGs (MLP 6 -> 12) so iteration c+1's
            // loads overlap iteration c's MUFU/FMA work.
            #pragma unroll 2
            for (int c = 0; c < CC; c++) {
                const float* r0 = base + c * PLANE;
                float r00 = __ldg(r0 + 0),  r01 = __ldg(r0 + 1),  r02 = __ldg(r0 + off2);
                float r10 = __ldg(r0 + SW), r11 = __ldg(r0 + SW + 1), r12 = __ldg(r0 + SW + off2);
                float h0 = fmaf(fy, r10 - r00, r00);
                float h1 = fmaf(fy, r11 - r01, r01);
                float h2 = fmaf(fy, r12 - r02, r02);
                float d0 = h1 - h0, d1 = h2 - h1;
                #pragma unroll
                for (int j = 0; j < 8; j++) {
                    float bb = ((omask >> j) & 1) ? h1 : h0;
                    float dd = ((omask >> j) & 1) ? d1 : d0;
                    float z  = fmaf(fx[j], dd, bb);
                    s[j] += __expf(z);                 // no max-sub: |z| small
                    zt[j] = (ts[j] == c) ? z : zt[j];
                }
            }

            #pragma unroll
            for (int j = 0; j < 8; j++) {
                if (j < npix) {
                    float lp = zt[j] - __logf(s[j]);
                    uint32_t k = ((vmask >> j) & 1) ? f2key(lp) : 0xFFFFFFFFu;
                    g_keys[pi][pixbase + j] = k;
                    atomicAdd(&sh_hist[pi][k >> 24], 1u);   // radix pass 0, fused
                }
            }
        }
    }
    unsigned int wsum = __reduce_add_sync(0xFFFFFFFFu, (unsigned int)validcnt);
    if ((threadIdx.x & 31) == 0 && wsum) atomicAdd(&g_numvalid, wsum);

    __syncthreads();
    for (int i = threadIdx.x; i < 512; i += blockDim.x) {
        unsigned int v = (&sh_hist[0][0])[i];
        if (v) atomicAdd(&g_hist[i >> 8][0][i & 255], v);
    }
}

// ---------------- radix select passes 1..3 ----------------
// NPIX = 2,365,444 = 4 * 591,361 -> exact uint4 coverage.
#define NPIX4 (NPIX/4)
__global__ void hist_kernel(int pass) {
    __shared__ unsigned int sh[256];
    int pred = blockIdx.y;
    for (int i = threadIdx.x; i < 256; i += blockDim.x) sh[i] = 0u;
    __syncthreads();
    unsigned int pref = g_prefix[pred];
    int shift = 24 - 8 * pass;
    const uint4* keys4 = (const uint4*)&g_keys[pred][0];
    for (long long i = (long long)blockIdx.x * blockDim.x + threadIdx.x; i < NPIX4;
         i += (long long)gridDim.x * blockDim.x) {
        uint4 kv = __ldg(keys4 + i);
        if ((kv.x >> (shift + 8)) == pref) atomicAdd(&sh[(kv.x >> shift) & 255u], 1u);
        if ((kv.y >> (shift + 8)) == pref) atomicAdd(&sh[(kv.y >> shift) & 255u], 1u);
        if ((kv.z >> (shift + 8)) == pref) atomicAdd(&sh[(kv.z >> shift) & 255u], 1u);
        if ((kv.w >> (shift + 8)) == pref) atomicAdd(&sh[(kv.w >> shift) & 255u], 1u);
    }
    __syncthreads();
    for (int i = threadIdx.x; i < 256; i += blockDim.x) {
        unsigned int v = sh[i];
        if (v) atomicAdd(&g_hist[pred][pass][i], v);
    }
}

// ---------------- parallel bucket find (256 threads, 1 block) ----------------
// Each thread owns one of the 256 bins; cooperative prefix-scan locates the
// bucket containing the k-th element. Replaces 512 serialized L2-latency
// loads (measured 10.4us) with 2 parallel loads + ~60 cycles of scan.
__global__ void find_kernel(int pass) {
    __shared__ unsigned int warpsum[8];
    __shared__ unsigned int s_bsel, s_krem;
    int t = threadIdx.x;            // 0..255
    int lane = t & 31, w = t >> 5;

    #pragma unroll 1
    for (int pred = 0; pred < 2; pred++) {
        if (t == 0) { s_bsel = 255u; s_krem = 0u; }
        __syncthreads();

        long long kr0;
        if (pass == 0) {
            unsigned int nv = g_numvalid;
            long long kk = (long long)(nv < (unsigned)MINKEPT ? nv : (unsigned)MINKEPT) - 1;
            if (kk < 0) kk = 0;
            kr0 = kk;
            if (t == 0 && pred == 0) g_keepall = ((unsigned)MINKEPT >= nv) ? 1 : 0;
        } else {
            kr0 = g_krem[pred];
        }

        unsigned int cnt = g_hist[pred][pass][t];
        // inclusive scan within warp
        unsigned int incl = cnt;
        #pragma unroll
        for (int st = 1; st < 32; st <<= 1) {
            unsigned int v = __shfl_up_sync(0xFFFFFFFFu, incl, st);
            if (lane >= st) incl += v;
        }
        if (lane == 31) warpsum[w] = incl;
        __syncthreads();
        unsigned int woff = 0;
        #pragma unroll
        for (int i = 0; i < 8; i++) woff += (i < w) ? warpsum[i] : 0u;
        unsigned int inclusive = incl + woff;
        unsigned int exclusive = inclusive - cnt;

        if (kr0 >= (long long)exclusive && kr0 < (long long)inclusive) {
            s_bsel = (unsigned)t;
            s_krem = (unsigned)(kr0 - exclusive);
        }
        __syncthreads();

        if (t == 0) {
            g_prefix[pred] = ((pass == 0) ? 0u : (g_prefix[pred] << 8)) | s_bsel;
            g_krem[pred] = (int)s_krem;
            if (pass == 3) {
                // log-domain threshold: max(lp_kth, ln 0.7). Monotone-exact:
                // p <= max(p_kth, 0.7)  <=>  lp <= max(lp_kth, ln 0.7)
                float lp = key2f(g_prefix[pred]);
                g_logth[pred] = (lp > LOG_THR) ? lp : LOG_THR;
            }
        }
        __syncthreads();   // protect warpsum/s_* reuse next pred
    }
}

// ---------------- final weighted reduction (+ fin fused, last block) --------
__global__ void sum_kernel(float* __restrict__ out) {
    int pred = blockIdx.y;
    int keepall = g_keepall;
    float lth = g_logth[pred];
    float sw = 0.f, swl = 0.f;
    for (long long i = (long long)blockIdx.x * blockDim.x + threadIdx.x; i < NPIX;
         i += (long long)SUM_BLOCKS * blockDim.x) {
        uint32_t k = g_keys[pred][i];
        if (k == 0xFFFFFFFFu) continue;                // invalid pixel
        float lp = key2f(k);
        if (!keepall && (lp > lth)) continue;          // OHEM filter (log-domain)
        float w = c_w[g_cls[i]];
        sw += w; swl += w * (-lp);
    }
    // warp shuffle reduction, then 8-lane smem combine
    #pragma unroll
    for (int st = 16; st > 0; st >>= 1) {
        sw  += __shfl_down_sync(0xFFFFFFFFu, sw, st);
        swl += __shfl_down_sync(0xFFFFFFFFu, swl, st);
    }
    __shared__ float red[2][8];
    int wid = threadIdx.x >> 5, lid = threadIdx.x & 31;
    if (lid == 0) { red[0][wid] = sw; red[1][wid] = swl; }
    __syncthreads();
    if (wid == 0) {
        sw  = (lid < (blockDim.x >> 5)) ? red[0][lid] : 0.f;
        swl = (lid < (blockDim.x >> 5)) ? red[1][lid] : 0.f;
        #pragma unroll
        for (int st = 4; st > 0; st >>= 1) {
            sw  += __shfl_down_sync(0xFFu, sw, st);
            swl += __shfl_down_sync(0xFFu, swl, st);
        }
        if (lid == 0) {
            atomicAdd(&g_sums[pred * 2 + 0], (double)sw);
            atomicAdd(&g_sums[pred * 2 + 1], (double)swl);
            __threadfence();
            unsigned int done = atomicAdd(&g_bdone, 1u);
            if (done == (unsigned)(SUM_BLOCKS * 2 - 1)) {    // last block: finalize
                float L1 = (float)(g_sums[1] / g_sums[0]);
                float L2 = (float)(g_sums[3] / g_sums[2]);
                out[0] = 0.4f * L1 + L2;
            }
        }
    }
}

// ---------------- launch ----------------
extern "C" void kernel_launch(void* const* d_in, const int* in_sizes, int n_in,
                              void* d_out, int out_size)
{
    // identify inputs: preds have exactly PRED_ELEMS elements (unique count);
    // the target is whatever remains (size NPIX for int32/int64 element counts,
    // or 2*NPIX if the harness reports int64 as 32-bit words).
    const float* preds[2] = { nullptr, nullptr };
    const void* tg = nullptr;
    int pi = 0;
    for (int i = 0; i < n_in && i < 3; i++) {
        if (in_sizes[i] == PRED_ELEMS && pi < 2) preds[pi++] = (const float*)d_in[i];
        else tg = d_in[i];
    }
    // positional fallback (metadata order: pred1, pred2, target)
    if (!tg || pi < 2) {
        preds[0] = (const float*)d_in[0];
        preds[1] = (const float*)d_in[1];
        tg = d_in[2];
    }

    init_kernel<<<1, 64>>>((const int*)tg);

    int nb = (NSTRIPS + 127) / 128;
    main_kernel<<<nb, 128>>>(preds[0], preds[1], tg);

    find_kernel<<<1, 256>>>(0);                   // pass-0 hist fused into main
    for (int pass = 1; pass < 4; pass++) {
        hist_kernel<<<dim3(512, 2), 256>>>(pass);
        find_kernel<<<1, 256>>>(pass);
    }

    sum_kernel<<<dim3(SUM_BLOCKS, 2), 256>>>((float*)d_out);
}